// round 7
// baseline (speedup 1.0000x reference)
#include <cuda_runtime.h>
#include <cstdint>

#define T_LEN 4096
#define E_DIM 256
#define H_DIM 256
#define G_DIM 1024   // 4*H
#define L_TAGS 18
#define START_TAG 16
#define STOP_TAG 17
#define NEGV (-10000.0f)

// ---------------- device scratch (static: no allocations allowed) ----------
__device__ float g_pre[2][(size_t)T_LEN * G_DIM];   // pre-activations, fwd/bwd
__device__ float g_h[2][(size_t)T_LEN * H_DIM];     // hf / hb
__device__ float g_emit[(size_t)T_LEN * L_TAGS];    // emissions

// ---------------- small helpers -------------------------------------------
__device__ __forceinline__ unsigned long long ffma2(unsigned long long a,
                                                    unsigned long long b,
                                                    unsigned long long c) {
    unsigned long long d;
    asm("fma.rn.f32x2 %0, %1, %2, %3;" : "=l"(d) : "l"(a), "l"(b), "l"(c));
    return d;
}
__device__ __forceinline__ float2 unpackf2(unsigned long long v) {
    float2 r;
    asm("mov.b64 {%0, %1}, %2;" : "=f"(r.x), "=f"(r.y) : "l"(v));
    return r;
}
__device__ __forceinline__ float sigmoidf_(float x) {
    return __fdividef(1.0f, 1.0f + __expf(-x));
}
__device__ __forceinline__ float tanh_fast(float x) {
    float e = __expf(2.0f * x);
    return 1.0f - __fdividef(2.0f, e + 1.0f);
}
__device__ __forceinline__ uint32_t smem_u32(const void* p) {
    uint32_t a;
    asm("{ .reg .u64 t; cvta.to.shared.u64 t, %1; cvt.u32.u64 %0, t; }"
        : "=r"(a) : "l"(p));
    return a;
}
__device__ __forceinline__ uint32_t mapa_u32(uint32_t local, uint32_t rank) {
    uint32_t r;
    asm("mapa.shared::cluster.u32 %0, %1, %2;" : "=r"(r) : "r"(local), "r"(rank));
    return r;
}
// direct DSMEM read from a peer CTA's shared memory
__device__ __forceinline__ float ld_cluster_f32(uint32_t addr) {
    uint32_t v;
    asm volatile("ld.shared::cluster.b32 %0, [%1];" : "=r"(v) : "r"(addr)
                 : "memory");
    return __uint_as_float(v);
}
__device__ __forceinline__ void cp_async16(uint32_t dst, const void* src) {
    asm volatile("cp.async.ca.shared.global [%0], [%1], 16;"
                 :: "r"(dst), "l"(src) : "memory");
}
__device__ __forceinline__ void cluster_arrive_rel() {
    asm volatile("barrier.cluster.arrive.release.aligned;" ::: "memory");
}
__device__ __forceinline__ void cluster_wait_acq() {
    asm volatile("barrier.cluster.wait.acquire.aligned;" ::: "memory");
}

// ---------------- 1) fused gather + input GEMM -----------------------------
__global__ __launch_bounds__(256) void gemm_pre_kernel(
    const int* __restrict__ feats, const float* __restrict__ emb,
    const float* __restrict__ wih_f, const float* __restrict__ wih_b,
    const float* __restrict__ b_f, const float* __restrict__ b_b) {
    int dir = blockIdx.z;
    const float* wih  = dir ? wih_b : wih_f;
    const float* bias = dir ? b_b : b_f;
    float* out = g_pre[dir];

    int m0 = blockIdx.y * 64;   // time tile
    int n0 = blockIdx.x * 64;   // gate-row tile

    __shared__ __align__(16) float As[64][68];
    __shared__ __align__(16) float Bs[64][68];
    __shared__ int fid[64];

    int tid = threadIdx.x;
    int tx = tid & 15, ty = tid >> 4;

    if (tid < 64) fid[tid] = feats[m0 + tid];
    __syncthreads();

    float acc[4][4];
#pragma unroll
    for (int i = 0; i < 4; i++)
#pragma unroll
        for (int j = 0; j < 4; j++) acc[i][j] = 0.f;

    for (int kb = 0; kb < 4; kb++) {
#pragma unroll
        for (int i = 0; i < 16; i++) {
            int idx = tid + i * 256;
            int m = idx >> 6, k = idx & 63;
            As[k][m] = emb[(size_t)fid[m] * E_DIM + kb * 64 + k];
            Bs[k][m] = wih[(size_t)(n0 + m) * E_DIM + kb * 64 + k];
        }
        __syncthreads();
#pragma unroll
        for (int k = 0; k < 64; k++) {
            float4 a4 = *(const float4*)&As[k][ty * 4];
            float4 b4 = *(const float4*)&Bs[k][tx * 4];
            float av[4] = {a4.x, a4.y, a4.z, a4.w};
            float bv[4] = {b4.x, b4.y, b4.z, b4.w};
#pragma unroll
            for (int i = 0; i < 4; i++)
#pragma unroll
                for (int j = 0; j < 4; j++) acc[i][j] += av[i] * bv[j];
        }
        __syncthreads();
    }
#pragma unroll
    for (int j = 0; j < 4; j++) {
        float bj = bias[n0 + tx * 4 + j];
#pragma unroll
        for (int i = 0; i < 4; i++)
            out[(size_t)(m0 + ty * 4 + i) * G_DIM + n0 + tx * 4 + j] =
                acc[i][j] + bj;
    }
}

// ---------------- 2) LSTM recurrence: 8-CTA cluster, CONSUMER-PULL ---------
// No async proxy, no mbarriers. Per step:
//   matvec (all warps, hsm[b]) -> gsum -> __syncthreads
//   warp 0: dense gates -> h -> STS hstage[b^1]
//   barrier.cluster.arrive.release (warp0 last) / wait.acquire
//   warps 8-15: pull source k's 32 h via ld.shared::cluster -> hsm[b^1]
//   __syncthreads
__global__ void __cluster_dims__(8, 1, 1) __launch_bounds__(512, 1)
lstm_cluster_kernel(const float* __restrict__ whh_f,
                    const float* __restrict__ whh_b) {
    __shared__ __align__(16) float hsm[2][272];        // padded h, dbl-buffered
    __shared__ __align__(16) float pre_s[3][16][144];  // 16 steps x 4x36
    __shared__ __align__(16) float gsum[32][4];        // gate sums [unit][gate]
    __shared__ __align__(16) float hstage[2][32];      // fresh h per buffer

    uint32_t rank;
    asm("mov.u32 %0, %%cluster_ctarank;" : "=r"(rank));
    int dir = blockIdx.x >> 3;

    const float* whh = dir ? whh_b : whh_f;
    const float* pre = g_pre[dir];
    float* hout = g_h[dir];

    int tid = threadIdx.x;
    int lane = tid & 31, warp = tid >> 5;
    int g = lane & 3;              // column group [64g, 64g+64)
    int gate = (lane >> 2) & 3;    // i,f,g,o
    int u2 = lane >> 4;            // unit within warp pair
    int unit_local = warp * 2 + u2;           // 0..31
    int k_unit = (int)rank * 32 + unit_local; // global hidden unit
    int grow = gate * 256 + k_unit;           // global gate row

    // register-resident weights: 64 floats = 32 packed f32x2
    unsigned long long wr[32];
    {
        const ulonglong2* wp =
            (const ulonglong2*)(whh + (size_t)grow * H_DIM + g * 64);
#pragma unroll
        for (int q = 0; q < 16; q++) {
            ulonglong2 v = wp[q];
            wr[2 * q] = v.x;
            wr[2 * q + 1] = v.y;
        }
    }

    for (int i = tid; i < 272; i += 512) { hsm[0][i] = 0.f; hsm[1][i] = 0.f; }

    uint32_t pbase = smem_u32(&pre_s[0][0][0]);
    uint32_t sbase = smem_u32(&hstage[0][0]);

    // --- pre[] chunk loader lane mapping (1 x 16B per thread per chunk) ---
    int c_step = tid >> 5;          // 0..15: step within chunk
    int c_sub = tid & 31;
    int c_gate = c_sub >> 3, c_l8 = c_sub & 7;

    // prologue: issue chunks 0 and 1
#pragma unroll
    for (int ck = 0; ck < 2; ck++) {
        int ss = ck * 16 + c_step;
        int t = dir ? (T_LEN - 1 - ss) : ss;
        const float* src =
            pre + (size_t)t * G_DIM + c_gate * 256 + (int)rank * 32 + c_l8 * 4;
        uint32_t dst = pbase +
            (uint32_t)((ck * 16 + c_step) * 144 + c_gate * 36 + c_l8 * 4) * 4u;
        cp_async16(dst, src);
        asm volatile("cp.async.commit_group;" ::: "memory");
    }

    // puller setup: warp 8+k pulls source CTA k's hstage (32 floats, 1/lane)
    int pk = warp - 8;                       // source CTA for puller warps
    uint32_t srcA = 0, srcB = 0;             // remote addr, buffer 0 / 1
    int pdst = 0;                            // local hsm slot (padded)
    if (warp >= 8) {
        srcA = mapa_u32(sbase + (uint32_t)lane * 4u, (uint32_t)pk);
        srcB = mapa_u32(sbase + (uint32_t)(32 + lane) * 4u, (uint32_t)pk);
        pdst = (pk >> 1) * 68 + (pk & 1) * 32 + lane;
    }

    __syncthreads();
    cluster_arrive_rel();
    cluster_wait_acq();

    float c = 0.f;                 // cell state: warp 0, lane = unit

    for (int s = 0; s < T_LEN; s++) {
        int b = s & 1;
        int si = s & 15;
        int t = dir ? (T_LEN - 1 - s) : s;

        if (si == 0) {
            int c2 = (s >> 4) + 2;
            if (c2 < (T_LEN / 16)) {
                int ss = c2 * 16 + c_step;
                int tt = dir ? (T_LEN - 1 - ss) : ss;
                const float* src = pre + (size_t)tt * G_DIM + c_gate * 256 +
                                   (int)rank * 32 + c_l8 * 4;
                uint32_t dst = pbase +
                    (uint32_t)(((c2 % 3) * 16 + c_step) * 144 +
                               c_gate * 36 + c_l8 * 4) * 4u;
                cp_async16(dst, src);
                asm volatile("cp.async.commit_group;" ::: "memory");
                asm volatile("cp.async.wait_group 2;" ::: "memory");
            } else {
                asm volatile("cp.async.wait_group 0;" ::: "memory");
            }
            __syncthreads();
        }
        int buf = (s >> 4) % 3;

        // pre value from SMEM
        float p = 0.f;
        if (g == 0) p = pre_s[buf][si][gate * 36 + unit_local];

        // matvec: 64 weights vs h[64g .. 64g+64), 4 parallel FMA chains
        const ulonglong2* h2 = (const ulonglong2*)(&hsm[b][g * 68]);
        unsigned long long a0 = 0ull, a1 = 0ull, a2 = 0ull, a3 = 0ull;
#pragma unroll
        for (int q = 0; q < 8; q++) {
            ulonglong2 hv0 = h2[q];
            ulonglong2 hv1 = h2[q + 8];
            a0 = ffma2(wr[2 * q], hv0.x, a0);
            a1 = ffma2(wr[2 * q + 1], hv0.y, a1);
            a2 = ffma2(wr[2 * q + 16], hv1.x, a2);
            a3 = ffma2(wr[2 * q + 17], hv1.y, a3);
        }
        float2 f0 = unpackf2(a0), f1 = unpackf2(a1);
        float2 f2 = unpackf2(a2), f3 = unpackf2(a3);
        float sum = ((f0.x + f0.y) + (f1.x + f1.y)) +
                    ((f2.x + f2.y) + (f3.x + f3.y));
        sum += __shfl_xor_sync(0xffffffffu, sum, 1);
        sum += __shfl_xor_sync(0xffffffffu, sum, 2);

        // g==0 lanes deposit this unit's gate sum (conflict-free layout)
        if (g == 0) gsum[unit_local][gate] = sum + p;
        __syncthreads();

        float h = 0.f;
        if (warp == 0) {
            float4 gv = *(const float4*)&gsum[lane][0];   // i,f,g,o
            float ii = sigmoidf_(gv.x);
            float ff = sigmoidf_(gv.y);
            float oo = sigmoidf_(gv.w);
            c = ff * c + ii * tanh_fast(gv.z);
            h = oo * tanh_fast(c);
            hstage[b ^ 1][lane] = h;          // plain STS, no proxy
        }

        // cluster handshake: warps 1-15 arrive early; warp 0 after its STS
        cluster_arrive_rel();
        if (warp == 0)
            hout[(size_t)t * H_DIM + (int)rank * 32 + lane] = h;  // off-path
        cluster_wait_acq();

        // pull: warp 8+k fetches source k's fresh block into hsm[b^1]
        if (warp >= 8) {
            float v = ld_cluster_f32(b ? srcA : srcB);  // step-s h in buf b^1
            hsm[b ^ 1][pdst] = v;
        }
        __syncthreads();
    }

    // final full-cluster handshake: no CTA exits while peers may still pull
    cluster_arrive_rel();
    cluster_wait_acq();
}

// ---------------- 3) emit = [hf|hb] @ W_out.T + b_out ----------------------
__global__ __launch_bounds__(128) void emit_kernel(
    const float* __restrict__ Wout, const float* __restrict__ bout) {
    int t = blockIdx.x;
    __shared__ float h[512];
    __shared__ float part[4][18];
    int tid = threadIdx.x;

    h[tid]       = g_h[0][(size_t)t * 256 + tid];
    h[tid + 128] = g_h[0][(size_t)t * 256 + 128 + tid];
    h[tid + 256] = g_h[1][(size_t)t * 256 + tid];
    h[tid + 384] = g_h[1][(size_t)t * 256 + 128 + tid];
    __syncthreads();

    if (tid < 72) {
        int jj = tid >> 2, q = tid & 3;
        const float* w = Wout + (size_t)jj * 512 + q * 128;
        const float* hh = h + q * 128;
        float a0 = 0.f, a1 = 0.f, a2 = 0.f, a3 = 0.f;
#pragma unroll
        for (int k = 0; k < 128; k += 4) {
            a0 += hh[k] * w[k];
            a1 += hh[k + 1] * w[k + 1];
            a2 += hh[k + 2] * w[k + 2];
            a3 += hh[k + 3] * w[k + 3];
        }
        part[q][jj] = (a0 + a1) + (a2 + a3);
    }
    __syncthreads();
    if (tid < 18)
        g_emit[(size_t)t * L_TAGS + tid] =
            part[0][tid] + part[1][tid] + part[2][tid] + part[3][tid] + bout[tid];
}

// ---------------- 4) Viterbi + backtrack (one warp) -------------------------
__global__ void viterbi_kernel(const float* __restrict__ trans,
                               float* __restrict__ out, int write_score) {
    extern __shared__ unsigned char bp[];   // T_LEN * L_TAGS backpointers
    int j = threadIdx.x;
    bool act = (j < L_TAGS);

    float tcol[L_TAGS];
#pragma unroll
    for (int i = 0; i < L_TAGS; i++)
        tcol[i] = act ? trans[i * L_TAGS + j] : 0.f;

    float fv = act ? ((j == START_TAG) ? 0.f : NEGV) : -3.0e38f;
    float e = act ? g_emit[j] : 0.f;

    for (int t = 0; t < T_LEN; t++) {
        float e_next = (act && t + 1 < T_LEN)
                           ? g_emit[(size_t)(t + 1) * L_TAGS + j] : 0.f;
        float b0 = -3.4e38f, b1 = -3.4e38f, b2 = -3.4e38f;
        int a0 = 0, a1 = 6, a2 = 12;
#pragma unroll
        for (int i = 0; i < 6; i++) {
            float s0 = __shfl_sync(0xffffffffu, fv, i) + tcol[i];
            float s1 = __shfl_sync(0xffffffffu, fv, i + 6) + tcol[i + 6];
            float s2 = __shfl_sync(0xffffffffu, fv, i + 12) + tcol[i + 12];
            if (s0 > b0) { b0 = s0; a0 = i; }
            if (s1 > b1) { b1 = s1; a1 = i + 6; }
            if (s2 > b2) { b2 = s2; a2 = i + 12; }
        }
        float best = b0; int arg = a0;
        if (b1 > best) { best = b1; arg = a1; }
        if (b2 > best) { best = b2; arg = a2; }

        if (act) {
            bp[t * L_TAGS + j] = (unsigned char)arg;
            fv = best + e;
        }
        e = e_next;
    }

    float term = act ? (fv + trans[j * L_TAGS + STOP_TAG]) : -3.4e38f;
    int ai = j;
#pragma unroll
    for (int off = 16; off > 0; off >>= 1) {
        float ov = __shfl_xor_sync(0xffffffffu, term, off);
        int oi = __shfl_xor_sync(0xffffffffu, ai, off);
        if (ov > term || (ov == term && oi < ai)) { term = ov; ai = oi; }
    }

    if (j == 0) {
        if (write_score) out[0] = term;
        float* path = out + write_score;
        int tag = ai;
        for (int t = T_LEN - 1; t >= 0; t--) {
            path[t] = (float)tag;
            tag = bp[t * L_TAGS + tag];
        }
    }
}

// ---------------- launch ----------------------------------------------------
extern "C" void kernel_launch(void* const* d_in, const int* in_sizes, int n_in,
                              void* d_out, int out_size) {
    const int*   feats  = (const int*)d_in[0];
    const float* emb    = (const float*)d_in[1];
    const float* w_ih_f = (const float*)d_in[2];
    const float* w_hh_f = (const float*)d_in[3];
    const float* b_f    = (const float*)d_in[4];
    const float* w_ih_b = (const float*)d_in[5];
    const float* w_hh_b = (const float*)d_in[6];
    const float* b_b    = (const float*)d_in[7];
    const float* W_out  = (const float*)d_in[8];
    const float* b_out  = (const float*)d_in[9];
    const float* trans  = (const float*)d_in[10];

    dim3 gg(G_DIM / 64, T_LEN / 64, 2);
    gemm_pre_kernel<<<gg, 256>>>(feats, emb, w_ih_f, w_ih_b, b_f, b_b);

    lstm_cluster_kernel<<<16, 512>>>(w_hh_f, w_hh_b);

    emit_kernel<<<T_LEN, 128>>>(W_out, b_out);

    int ws = (out_size > T_LEN) ? 1 : 0;   // layout: [path_score, path...]
    static int smem_set = 0;
    if (!smem_set) {
        cudaFuncSetAttribute(viterbi_kernel,
                             cudaFuncAttributeMaxDynamicSharedMemorySize,
                             T_LEN * L_TAGS + 1024);
        smem_set = 1;
    }
    viterbi_kernel<<<1, 32, T_LEN * L_TAGS>>>(trans, (float*)d_out, ws);
}

// round 8
// speedup vs baseline: 1.2357x; 1.2357x over previous
#include <cuda_runtime.h>
#include <cstdint>

#define T_LEN 4096
#define E_DIM 256
#define H_DIM 256
#define G_DIM 1024   // 4*H
#define L_TAGS 18
#define START_TAG 16
#define STOP_TAG 17
#define NEGV (-10000.0f)

// ---------------- device scratch (static: no allocations allowed) ----------
__device__ float g_pre[2][(size_t)T_LEN * G_DIM];   // pre-activations, fwd/bwd
__device__ float g_h[2][(size_t)T_LEN * H_DIM];     // hf / hb
__device__ float g_emit[(size_t)T_LEN * L_TAGS];    // emissions

// ---------------- small helpers -------------------------------------------
__device__ __forceinline__ unsigned long long ffma2(unsigned long long a,
                                                    unsigned long long b,
                                                    unsigned long long c) {
    unsigned long long d;
    asm("fma.rn.f32x2 %0, %1, %2, %3;" : "=l"(d) : "l"(a), "l"(b), "l"(c));
    return d;
}
__device__ __forceinline__ float2 unpackf2(unsigned long long v) {
    float2 r;
    asm("mov.b64 {%0, %1}, %2;" : "=f"(r.x), "=f"(r.y) : "l"(v));
    return r;
}
__device__ __forceinline__ float sigmoidf_(float x) {
    return __fdividef(1.0f, 1.0f + __expf(-x));
}
__device__ __forceinline__ float tanh_fast(float x) {
    float e = __expf(2.0f * x);
    return 1.0f - __fdividef(2.0f, e + 1.0f);
}
__device__ __forceinline__ uint32_t smem_u32(const void* p) {
    uint32_t a;
    asm("{ .reg .u64 t; cvta.to.shared.u64 t, %1; cvt.u32.u64 %0, t; }"
        : "=r"(a) : "l"(p));
    return a;
}
__device__ __forceinline__ uint32_t mapa_u32(uint32_t local, uint32_t rank) {
    uint32_t r;
    asm("mapa.shared::cluster.u32 %0, %1, %2;" : "=r"(r) : "r"(local), "r"(rank));
    return r;
}
__device__ __forceinline__ void mbar_init(uint32_t mbar, uint32_t count) {
    asm volatile("mbarrier.init.shared::cta.b64 [%0], %1;" :: "r"(mbar), "r"(count)
                 : "memory");
}
__device__ __forceinline__ void mbar_expect_tx(uint32_t mbar, uint32_t bytes) {
    asm volatile("mbarrier.arrive.expect_tx.shared::cta.b64 _, [%0], %1;"
                 :: "r"(mbar), "r"(bytes) : "memory");
}
__device__ __forceinline__ void mbar_wait(uint32_t mbar, uint32_t parity) {
    asm volatile(
        "{\n\t.reg .pred P;\n\t"
        "W_%=:\n\t"
        "mbarrier.try_wait.parity.acquire.cta.shared::cta.b64 P, [%0], %1, 0x989680;\n\t"
        "@P bra.uni D_%=;\n\t"
        "bra.uni W_%=;\n\t"
        "D_%=:\n\t}"
        :: "r"(mbar), "r"(parity) : "memory");
}
// one-shot 128B SMEM -> remote-CTA SMEM with single tx update on remote mbar
__device__ __forceinline__ void bulk_s2cluster(uint32_t dst, uint32_t src,
                                               uint32_t bytes, uint32_t rmbar) {
    asm volatile(
        "cp.async.bulk.shared::cluster.shared::cta.mbarrier::complete_tx::bytes "
        "[%0], [%1], %2, [%3];"
        :: "r"(dst), "r"(src), "r"(bytes), "r"(rmbar) : "memory");
}
__device__ __forceinline__ void cp_async16(uint32_t dst, const void* src) {
    asm volatile("cp.async.ca.shared.global [%0], [%1], 16;"
                 :: "r"(dst), "l"(src) : "memory");
}

// ---------------- 1) fused gather + input GEMM -----------------------------
__global__ __launch_bounds__(256) void gemm_pre_kernel(
    const int* __restrict__ feats, const float* __restrict__ emb,
    const float* __restrict__ wih_f, const float* __restrict__ wih_b,
    const float* __restrict__ b_f, const float* __restrict__ b_b) {
    int dir = blockIdx.z;
    const float* wih  = dir ? wih_b : wih_f;
    const float* bias = dir ? b_b : b_f;
    float* out = g_pre[dir];

    int m0 = blockIdx.y * 64;
    int n0 = blockIdx.x * 64;

    __shared__ __align__(16) float As[64][68];
    __shared__ __align__(16) float Bs[64][68];
    __shared__ int fid[64];

    int tid = threadIdx.x;
    int tx = tid & 15, ty = tid >> 4;

    if (tid < 64) fid[tid] = feats[m0 + tid];
    __syncthreads();

    float acc[4][4];
#pragma unroll
    for (int i = 0; i < 4; i++)
#pragma unroll
        for (int j = 0; j < 4; j++) acc[i][j] = 0.f;

    for (int kb = 0; kb < 4; kb++) {
#pragma unroll
        for (int i = 0; i < 16; i++) {
            int idx = tid + i * 256;
            int m = idx >> 6, k = idx & 63;
            As[k][m] = emb[(size_t)fid[m] * E_DIM + kb * 64 + k];
            Bs[k][m] = wih[(size_t)(n0 + m) * E_DIM + kb * 64 + k];
        }
        __syncthreads();
#pragma unroll
        for (int k = 0; k < 64; k++) {
            float4 a4 = *(const float4*)&As[k][ty * 4];
            float4 b4 = *(const float4*)&Bs[k][tx * 4];
            float av[4] = {a4.x, a4.y, a4.z, a4.w};
            float bv[4] = {b4.x, b4.y, b4.z, b4.w};
#pragma unroll
            for (int i = 0; i < 4; i++)
#pragma unroll
                for (int j = 0; j < 4; j++) acc[i][j] += av[i] * bv[j];
        }
        __syncthreads();
    }
#pragma unroll
    for (int j = 0; j < 4; j++) {
        float bj = bias[n0 + tx * 4 + j];
#pragma unroll
        for (int i = 0; i < 4; i++)
            out[(size_t)(m0 + ty * 4 + i) * G_DIM + n0 + tx * 4 + j] =
                acc[i][j] + bj;
    }
}

// ---------------- 2) LSTM recurrence: 8-CTA cluster, 256 threads -----------
// Tile: thread(unit u = warp*4 + lane>>3, colblock cb = lane&7) owns ALL 4
// gate rows of unit u over cols [32cb, 32cb+32): 128 weight regs, 8 LDS.128
// of h per step (4x fewer SMEM bytes than before), 128 FMAs.
// h layout: col j -> 36*(j>>5) + (j&31)  (8 blocks hit all 32 banks).
// Broadcast: warp0 lanes0-7 bulk-ship this CTA's 128B h block to each peer.
__global__ void __cluster_dims__(8, 1, 1) __launch_bounds__(256, 1)
lstm_cluster_kernel(const float* __restrict__ whh_f,
                    const float* __restrict__ whh_b) {
    __shared__ __align__(16) float hsm[2][288];        // 36-stride padded h
    __shared__ __align__(16) float pre_s[3][16][144];  // 16 steps x 4x36
    __shared__ __align__(16) float hstage[2][32];      // fresh h (dbl-buffered)
    __shared__ __align__(8) unsigned long long mbar_sm[2];

    uint32_t rank;
    asm("mov.u32 %0, %%cluster_ctarank;" : "=r"(rank));
    int dir = blockIdx.x >> 3;

    const float* whh = dir ? whh_b : whh_f;
    const float* pre = g_pre[dir];
    float* hout = g_h[dir];

    int tid = threadIdx.x;
    int lane = tid & 31, warp = tid >> 5;       // 8 warps
    int cb = lane & 7;                          // column block [32cb,32cb+32)
    int ub = lane >> 3;                         // unit within warp (0..3)
    int unit = warp * 4 + ub;                   // local unit 0..31
    int k_unit = (int)rank * 32 + unit;         // global hidden unit

    // weights: all 4 gates of this unit, 32 cols -> 128 floats = 64 f32x2
    unsigned long long wr[4][16];
#pragma unroll
    for (int gg = 0; gg < 4; gg++) {
        const ulonglong2* wp = (const ulonglong2*)(
            whh + (size_t)(gg * 256 + k_unit) * H_DIM + cb * 32);
#pragma unroll
        for (int q = 0; q < 8; q++) {
            ulonglong2 v = wp[q];
            wr[gg][2 * q] = v.x;
            wr[gg][2 * q + 1] = v.y;
        }
    }

    for (int i = tid; i < 288; i += 256) { hsm[0][i] = 0.f; hsm[1][i] = 0.f; }

    uint32_t hbase = smem_u32(&hsm[0][0]);
    uint32_t pbase = smem_u32(&pre_s[0][0][0]);
    uint32_t sbase = smem_u32(&hstage[0][0]);
    uint32_t mb0 = smem_u32(&mbar_sm[0]);
    uint32_t mb1 = smem_u32(&mbar_sm[1]);

    if (tid == 0) {
        mbar_init(mb0, 1);
        mbar_init(mb1, 1);
        mbar_expect_tx(mb1, 1024);   // step-0 sends land on mb1
    }

    // pre loader: per chunk 16 steps x 128 floats = 512 x 16B pieces,
    // 256 threads x 2 pieces
    // piece idx: si = idx>>5, gate = (idx&31)>>3, l8 = idx&7
#define PRE_ISSUE(ck, ring)                                                   \
    do {                                                                      \
        _Pragma("unroll")                                                     \
        for (int pp = 0; pp < 2; pp++) {                                      \
            int idx = tid + pp * 256;                                         \
            int si_ = idx >> 5;                                               \
            int ga_ = (idx & 31) >> 3, l8_ = idx & 7;                         \
            int ss_ = (ck) * 16 + si_;                                        \
            int tt_ = dir ? (T_LEN - 1 - ss_) : ss_;                          \
            const float* src_ = pre + (size_t)tt_ * G_DIM + ga_ * 256 +       \
                                (int)rank * 32 + l8_ * 4;                     \
            uint32_t dst_ = pbase +                                           \
                (uint32_t)(((ring) * 16 + si_) * 144 + ga_ * 36 + l8_ * 4) * 4u; \
            cp_async16(dst_, src_);                                           \
        }                                                                     \
        asm volatile("cp.async.commit_group;" ::: "memory");                  \
    } while (0)

    PRE_ISSUE(0, 0);
    PRE_ISSUE(1, 1);

    // sender setup (warp 0 lanes 0-7): this CTA's 32 h = 128B contiguous at
    // float-offset 36*rank in every CTA's hsm buffer.
    uint32_t dst_b0 = 0, dst_b1 = 0, mdst0 = 0, mdst1 = 0;
    if (warp == 0 && lane < 8) {
        dst_b0 = mapa_u32(hbase + (uint32_t)(36 * rank) * 4u, (uint32_t)lane);
        dst_b1 = mapa_u32(hbase + (uint32_t)(288 + 36 * rank) * 4u, (uint32_t)lane);
        mdst0 = mapa_u32(mb0, (uint32_t)lane);
        mdst1 = mapa_u32(mb1, (uint32_t)lane);
    }

    __syncthreads();
    asm volatile("barrier.cluster.arrive.aligned;" ::: "memory");
    asm volatile("barrier.cluster.wait.aligned;" ::: "memory");

    float c = 0.f;                 // cell state lives in cb==0 lanes
    uint32_t par0 = 0, par1 = 0;

    for (int s = 0; s < T_LEN; s++) {
        int b = s & 1;
        int si = s & 15;
        int t = dir ? (T_LEN - 1 - s) : s;

        if (si == 0) {
            int c2 = (s >> 4) + 2;
            if (c2 < (T_LEN / 16)) {
                PRE_ISSUE(c2, c2 % 3);
                asm volatile("cp.async.wait_group 2;" ::: "memory");
            } else {
                asm volatile("cp.async.wait_group 0;" ::: "memory");
            }
            __syncthreads();
        }
        int buf = (s >> 4) % 3;

        // pre for gate cb of this unit (only cb<4 lanes need it)
        float p = (cb < 4) ? pre_s[buf][si][cb * 36 + unit] : 0.f;

        // wait until all 8 source CTAs delivered h for this step
        if (s > 0) {
            if (b) { mbar_wait(mb1, par1); par1 ^= 1; }
            else   { mbar_wait(mb0, par0); par0 ^= 1; }
        }
        if (tid == 0) mbar_expect_tx(b ? mb1 : mb0, 1024);

        // matvec: 4 gate rows x 32 cols; h from hsm[b] block cb
        const ulonglong2* h2 = (const ulonglong2*)(&hsm[b][cb * 36]);
        unsigned long long a0 = 0ull, a1 = 0ull, a2 = 0ull, a3 = 0ull;
#pragma unroll
        for (int q = 0; q < 8; q++) {
            ulonglong2 hv = h2[q];
            a0 = ffma2(wr[0][2 * q], hv.x, a0);
            a1 = ffma2(wr[1][2 * q], hv.x, a1);
            a2 = ffma2(wr[2][2 * q], hv.x, a2);
            a3 = ffma2(wr[3][2 * q], hv.x, a3);
            a0 = ffma2(wr[0][2 * q + 1], hv.y, a0);
            a1 = ffma2(wr[1][2 * q + 1], hv.y, a1);
            a2 = ffma2(wr[2][2 * q + 1], hv.y, a2);
            a3 = ffma2(wr[3][2 * q + 1], hv.y, a3);
        }
        float2 f0 = unpackf2(a0), f1 = unpackf2(a1);
        float2 f2 = unpackf2(a2), f3 = unpackf2(a3);
        float s0 = f0.x + f0.y, s1 = f1.x + f1.y;
        float s2 = f2.x + f2.y, s3 = f3.x + f3.y;

        // add pre at lane cb==gate (before reduction)
        if (cb == 0) s0 += p;
        else if (cb == 1) s1 += p;
        else if (cb == 2) s2 += p;
        else if (cb == 3) s3 += p;

        // reduce over the 8 col-blocks (lane bits 0-2)
#pragma unroll
        for (int mk = 1; mk < 8; mk <<= 1) {
            s0 += __shfl_xor_sync(0xffffffffu, s0, mk);
            s1 += __shfl_xor_sync(0xffffffffu, s1, mk);
            s2 += __shfl_xor_sync(0xffffffffu, s2, mk);
            s3 += __shfl_xor_sync(0xffffffffu, s3, mk);
        }

        // gates at cb==0 lanes (4 per warp), one unit each
        if (cb == 0) {
            float ii = sigmoidf_(s0);
            float ff = sigmoidf_(s1);
            float oo = sigmoidf_(s3);
            c = ff * c + ii * tanh_fast(s2);
            float h = oo * tanh_fast(c);
            hstage[b ^ 1][unit] = h;
            hout[(size_t)t * H_DIM + k_unit] = h;   // off critical path
        }
        __syncthreads();   // hstage staged; all hsm[b] reads retired

        // warp 0 lanes 0-7: ship the 128B block to CTA 'lane', 1 tx each
        if (warp == 0 && lane < 8) {
            asm volatile("fence.proxy.async.shared::cta;" ::: "memory");
            uint32_t d = b ? dst_b0 : dst_b1;   // step-s output -> buffer b^1
            uint32_t m = b ? mdst0 : mdst1;
            bulk_s2cluster(d, sbase + (uint32_t)((b ^ 1) * 32) * 4u, 128u, m);
        }
    }

    // drain: final sends (step T-1, odd) targeted mb0; complete that phase
    mbar_wait(mb0, par0);
    asm volatile("barrier.cluster.arrive.aligned;" ::: "memory");
    asm volatile("barrier.cluster.wait.aligned;" ::: "memory");
#undef PRE_ISSUE
}

// ---------------- 3) emit = [hf|hb] @ W_out.T + b_out ----------------------
__global__ __launch_bounds__(128) void emit_kernel(
    const float* __restrict__ Wout, const float* __restrict__ bout) {
    int t = blockIdx.x;
    __shared__ float h[512];
    __shared__ float part[4][18];
    int tid = threadIdx.x;

    h[tid]       = g_h[0][(size_t)t * 256 + tid];
    h[tid + 128] = g_h[0][(size_t)t * 256 + 128 + tid];
    h[tid + 256] = g_h[1][(size_t)t * 256 + tid];
    h[tid + 384] = g_h[1][(size_t)t * 256 + 128 + tid];
    __syncthreads();

    if (tid < 72) {
        int jj = tid >> 2, q = tid & 3;
        const float* w = Wout + (size_t)jj * 512 + q * 128;
        const float* hh = h + q * 128;
        float a0 = 0.f, a1 = 0.f, a2 = 0.f, a3 = 0.f;
#pragma unroll
        for (int k = 0; k < 128; k += 4) {
            a0 += hh[k] * w[k];
            a1 += hh[k + 1] * w[k + 1];
            a2 += hh[k + 2] * w[k + 2];
            a3 += hh[k + 3] * w[k + 3];
        }
        part[q][jj] = (a0 + a1) + (a2 + a3);
    }
    __syncthreads();
    if (tid < 18)
        g_emit[(size_t)t * L_TAGS + tid] =
            part[0][tid] + part[1][tid] + part[2][tid] + part[3][tid] + bout[tid];
}

// ---------------- 4) Viterbi + backtrack (one warp) -------------------------
__global__ void viterbi_kernel(const float* __restrict__ trans,
                               float* __restrict__ out, int write_score) {
    extern __shared__ unsigned char bp[];
    int j = threadIdx.x;
    bool act = (j < L_TAGS);

    float tcol[L_TAGS];
#pragma unroll
    for (int i = 0; i < L_TAGS; i++)
        tcol[i] = act ? trans[i * L_TAGS + j] : 0.f;

    float fv = act ? ((j == START_TAG) ? 0.f : NEGV) : -3.0e38f;
    float e = act ? g_emit[j] : 0.f;

    for (int t = 0; t < T_LEN; t++) {
        float e_next = (act && t + 1 < T_LEN)
                           ? g_emit[(size_t)(t + 1) * L_TAGS + j] : 0.f;
        float b0 = -3.4e38f, b1 = -3.4e38f, b2 = -3.4e38f;
        int a0 = 0, a1 = 6, a2 = 12;
#pragma unroll
        for (int i = 0; i < 6; i++) {
            float s0 = __shfl_sync(0xffffffffu, fv, i) + tcol[i];
            float s1 = __shfl_sync(0xffffffffu, fv, i + 6) + tcol[i + 6];
            float s2 = __shfl_sync(0xffffffffu, fv, i + 12) + tcol[i + 12];
            if (s0 > b0) { b0 = s0; a0 = i; }
            if (s1 > b1) { b1 = s1; a1 = i + 6; }
            if (s2 > b2) { b2 = s2; a2 = i + 12; }
        }
        float best = b0; int arg = a0;
        if (b1 > best) { best = b1; arg = a1; }
        if (b2 > best) { best = b2; arg = a2; }

        if (act) {
            bp[t * L_TAGS + j] = (unsigned char)arg;
            fv = best + e;
        }
        e = e_next;
    }

    float term = act ? (fv + trans[j * L_TAGS + STOP_TAG]) : -3.4e38f;
    int ai = j;
#pragma unroll
    for (int off = 16; off > 0; off >>= 1) {
        float ov = __shfl_xor_sync(0xffffffffu, term, off);
        int oi = __shfl_xor_sync(0xffffffffu, ai, off);
        if (ov > term || (ov == term && oi < ai)) { term = ov; ai = oi; }
    }

    if (j == 0) {
        if (write_score) out[0] = term;
        float* path = out + write_score;
        int tag = ai;
        for (int t = T_LEN - 1; t >= 0; t--) {
            path[t] = (float)tag;
            tag = bp[t * L_TAGS + tag];
        }
    }
}

// ---------------- launch ----------------------------------------------------
extern "C" void kernel_launch(void* const* d_in, const int* in_sizes, int n_in,
                              void* d_out, int out_size) {
    const int*   feats  = (const int*)d_in[0];
    const float* emb    = (const float*)d_in[1];
    const float* w_ih_f = (const float*)d_in[2];
    const float* w_hh_f = (const float*)d_in[3];
    const float* b_f    = (const float*)d_in[4];
    const float* w_ih_b = (const float*)d_in[5];
    const float* w_hh_b = (const float*)d_in[6];
    const float* b_b    = (const float*)d_in[7];
    const float* W_out  = (const float*)d_in[8];
    const float* b_out  = (const float*)d_in[9];
    const float* trans  = (const float*)d_in[10];

    dim3 gg(G_DIM / 64, T_LEN / 64, 2);
    gemm_pre_kernel<<<gg, 256>>>(feats, emb, w_ih_f, w_ih_b, b_f, b_b);

    lstm_cluster_kernel<<<16, 256>>>(w_hh_f, w_hh_b);

    emit_kernel<<<T_LEN, 128>>>(W_out, b_out);

    int ws = (out_size > T_LEN) ? 1 : 0;   // layout: [path_score, path...]
    static int smem_set = 0;
    if (!smem_set) {
        cudaFuncSetAttribute(viterbi_kernel,
                             cudaFuncAttributeMaxDynamicSharedMemorySize,
                             T_LEN * L_TAGS + 1024);
        smem_set = 1;
    }
    viterbi_kernel<<<1, 32, T_LEN * L_TAGS>>>(trans, (float*)d_out, ws);
}

// round 9
// speedup vs baseline: 1.3541x; 1.0958x over previous
#include <cuda_runtime.h>
#include <cstdint>

#define T_LEN 4096
#define E_DIM 256
#define H_DIM 256
#define G_DIM 1024   // 4*H
#define L_TAGS 18
#define START_TAG 16
#define STOP_TAG 17
#define NEGV (-10000.0f)

// ---------------- device scratch (static: no allocations allowed) ----------
__device__ float g_pre[2][(size_t)T_LEN * G_DIM];   // pre-activations, fwd/bwd
__device__ float g_h[2][(size_t)T_LEN * H_DIM];     // hf / hb
__device__ float g_emit[(size_t)T_LEN * L_TAGS];    // emissions

// ---------------- small helpers -------------------------------------------
__device__ __forceinline__ unsigned long long ffma2(unsigned long long a,
                                                    unsigned long long b,
                                                    unsigned long long c) {
    unsigned long long d;
    asm("fma.rn.f32x2 %0, %1, %2, %3;" : "=l"(d) : "l"(a), "l"(b), "l"(c));
    return d;
}
__device__ __forceinline__ float2 unpackf2(unsigned long long v) {
    float2 r;
    asm("mov.b64 {%0, %1}, %2;" : "=f"(r.x), "=f"(r.y) : "l"(v));
    return r;
}
__device__ __forceinline__ float sigmoidf_(float x) {
    return __fdividef(1.0f, 1.0f + __expf(-x));
}
__device__ __forceinline__ float tanh_fast(float x) {
    float e = __expf(2.0f * x);
    return 1.0f - __fdividef(2.0f, e + 1.0f);
}
__device__ __forceinline__ uint32_t smem_u32(const void* p) {
    uint32_t a;
    asm("{ .reg .u64 t; cvta.to.shared.u64 t, %1; cvt.u32.u64 %0, t; }"
        : "=r"(a) : "l"(p));
    return a;
}
__device__ __forceinline__ uint32_t mapa_u32(uint32_t local, uint32_t rank) {
    uint32_t r;
    asm("mapa.shared::cluster.u32 %0, %1, %2;" : "=r"(r) : "r"(local), "r"(rank));
    return r;
}
__device__ __forceinline__ void mbar_init(uint32_t mbar, uint32_t count) {
    asm volatile("mbarrier.init.shared::cta.b64 [%0], %1;" :: "r"(mbar), "r"(count)
                 : "memory");
}
__device__ __forceinline__ void mbar_expect_tx(uint32_t mbar, uint32_t bytes) {
    asm volatile("mbarrier.arrive.expect_tx.shared::cta.b64 _, [%0], %1;"
                 :: "r"(mbar), "r"(bytes) : "memory");
}
// spin-then-sleep wait: one fast-path try_wait (no suspend hint, ~90cyc),
// then fall into the HW-sleep hinted loop.
__device__ __forceinline__ void mbar_wait(uint32_t mbar, uint32_t parity) {
    uint32_t done;
    asm volatile(
        "{\n\t.reg .pred P;\n\t"
        "mbarrier.try_wait.parity.acquire.cta.shared::cta.b64 P, [%1], %2;\n\t"
        "selp.b32 %0, 1, 0, P;\n\t}"
        : "=r"(done) : "r"(mbar), "r"(parity) : "memory");
    if (!done) {
        asm volatile(
            "{\n\t.reg .pred P;\n\t"
            "W_%=:\n\t"
            "mbarrier.try_wait.parity.acquire.cta.shared::cta.b64 P, [%0], %1, 0x989680;\n\t"
            "@P bra.uni D_%=;\n\t"
            "bra.uni W_%=;\n\t"
            "D_%=:\n\t}"
            :: "r"(mbar), "r"(parity) : "memory");
    }
}
// one-shot 128B SMEM -> remote-CTA SMEM with single tx update on remote mbar
__device__ __forceinline__ void bulk_s2cluster(uint32_t dst, uint32_t src,
                                               uint32_t bytes, uint32_t rmbar) {
    asm volatile(
        "cp.async.bulk.shared::cluster.shared::cta.mbarrier::complete_tx::bytes "
        "[%0], [%1], %2, [%3];"
        :: "r"(dst), "r"(src), "r"(bytes), "r"(rmbar) : "memory");
}
__device__ __forceinline__ void cp_async16(uint32_t dst, const void* src) {
    asm volatile("cp.async.ca.shared.global [%0], [%1], 16;"
                 :: "r"(dst), "l"(src) : "memory");
}

// ---------------- 1) fused gather + input GEMM -----------------------------
__global__ __launch_bounds__(256) void gemm_pre_kernel(
    const int* __restrict__ feats, const float* __restrict__ emb,
    const float* __restrict__ wih_f, const float* __restrict__ wih_b,
    const float* __restrict__ b_f, const float* __restrict__ b_b) {
    int dir = blockIdx.z;
    const float* wih  = dir ? wih_b : wih_f;
    const float* bias = dir ? b_b : b_f;
    float* out = g_pre[dir];

    int m0 = blockIdx.y * 64;
    int n0 = blockIdx.x * 64;

    __shared__ __align__(16) float As[64][68];
    __shared__ __align__(16) float Bs[64][68];
    __shared__ int fid[64];

    int tid = threadIdx.x;
    int tx = tid & 15, ty = tid >> 4;

    if (tid < 64) fid[tid] = feats[m0 + tid];
    __syncthreads();

    float acc[4][4];
#pragma unroll
    for (int i = 0; i < 4; i++)
#pragma unroll
        for (int j = 0; j < 4; j++) acc[i][j] = 0.f;

    for (int kb = 0; kb < 4; kb++) {
#pragma unroll
        for (int i = 0; i < 16; i++) {
            int idx = tid + i * 256;
            int m = idx >> 6, k = idx & 63;
            As[k][m] = emb[(size_t)fid[m] * E_DIM + kb * 64 + k];
            Bs[k][m] = wih[(size_t)(n0 + m) * E_DIM + kb * 64 + k];
        }
        __syncthreads();
#pragma unroll
        for (int k = 0; k < 64; k++) {
            float4 a4 = *(const float4*)&As[k][ty * 4];
            float4 b4 = *(const float4*)&Bs[k][tx * 4];
            float av[4] = {a4.x, a4.y, a4.z, a4.w};
            float bv[4] = {b4.x, b4.y, b4.z, b4.w};
#pragma unroll
            for (int i = 0; i < 4; i++)
#pragma unroll
                for (int j = 0; j < 4; j++) acc[i][j] += av[i] * bv[j];
        }
        __syncthreads();
    }
#pragma unroll
    for (int j = 0; j < 4; j++) {
        float bj = bias[n0 + tx * 4 + j];
#pragma unroll
        for (int i = 0; i < 4; i++)
            out[(size_t)(m0 + ty * 4 + i) * G_DIM + n0 + tx * 4 + j] =
                acc[i][j] + bj;
    }
}

// ---------------- 2) LSTM recurrence: 8-CTA cluster, 256 threads -----------
// Tile: thread(unit u = warp*4 + lane>>3, colblock cb = lane&7) owns ALL 4
// gate rows of unit u over cols [32cb, 32cb+32).
// Self-send eliminated: producers STS h into own hsm[b^1]; bulk to 7 peers,
// expect_tx = 896 bytes.
__global__ void __cluster_dims__(8, 1, 1) __launch_bounds__(256, 1)
lstm_cluster_kernel(const float* __restrict__ whh_f,
                    const float* __restrict__ whh_b) {
    __shared__ __align__(16) float hsm[2][288];        // 36-stride padded h
    __shared__ __align__(16) float pre_s[3][16][144];  // 16 steps x 4x36
    __shared__ __align__(16) float hstage[2][32];      // fresh h (dbl-buffered)
    __shared__ __align__(8) unsigned long long mbar_sm[2];

    uint32_t rank;
    asm("mov.u32 %0, %%cluster_ctarank;" : "=r"(rank));
    int dir = blockIdx.x >> 3;

    const float* whh = dir ? whh_b : whh_f;
    const float* pre = g_pre[dir];
    float* hout = g_h[dir];

    int tid = threadIdx.x;
    int lane = tid & 31, warp = tid >> 5;       // 8 warps
    int cb = lane & 7;                          // column block [32cb,32cb+32)
    int ub = lane >> 3;                         // unit within warp (0..3)
    int unit = warp * 4 + ub;                   // local unit 0..31
    int k_unit = (int)rank * 32 + unit;         // global hidden unit

    // weights: all 4 gates of this unit, 32 cols -> 128 floats = 64 f32x2
    unsigned long long wr[4][16];
#pragma unroll
    for (int gg = 0; gg < 4; gg++) {
        const ulonglong2* wp = (const ulonglong2*)(
            whh + (size_t)(gg * 256 + k_unit) * H_DIM + cb * 32);
#pragma unroll
        for (int q = 0; q < 8; q++) {
            ulonglong2 v = wp[q];
            wr[gg][2 * q] = v.x;
            wr[gg][2 * q + 1] = v.y;
        }
    }

    for (int i = tid; i < 288; i += 256) { hsm[0][i] = 0.f; hsm[1][i] = 0.f; }

    uint32_t hbase = smem_u32(&hsm[0][0]);
    uint32_t pbase = smem_u32(&pre_s[0][0][0]);
    uint32_t sbase = smem_u32(&hstage[0][0]);
    uint32_t mb0 = smem_u32(&mbar_sm[0]);
    uint32_t mb1 = smem_u32(&mbar_sm[1]);

    if (tid == 0) {
        mbar_init(mb0, 1);
        mbar_init(mb1, 1);
        mbar_expect_tx(mb1, 896);    // step-0 sends (7 peers) land on mb1
    }

#define PRE_ISSUE(ck, ring)                                                   \
    do {                                                                      \
        _Pragma("unroll")                                                     \
        for (int pp = 0; pp < 2; pp++) {                                      \
            int idx = tid + pp * 256;                                         \
            int si_ = idx >> 5;                                               \
            int ga_ = (idx & 31) >> 3, l8_ = idx & 7;                         \
            int ss_ = (ck) * 16 + si_;                                        \
            int tt_ = dir ? (T_LEN - 1 - ss_) : ss_;                          \
            const float* src_ = pre + (size_t)tt_ * G_DIM + ga_ * 256 +       \
                                (int)rank * 32 + l8_ * 4;                     \
            uint32_t dst_ = pbase +                                           \
                (uint32_t)(((ring) * 16 + si_) * 144 + ga_ * 36 + l8_ * 4) * 4u; \
            cp_async16(dst_, src_);                                           \
        }                                                                     \
        asm volatile("cp.async.commit_group;" ::: "memory");                  \
    } while (0)

    PRE_ISSUE(0, 0);
    PRE_ISSUE(1, 1);

    // sender setup (warp 0 lanes 0-7, skipping self): this CTA's 32 h =
    // 128B contiguous at float-offset 36*rank in every CTA's hsm buffer.
    uint32_t dst_b0 = 0, dst_b1 = 0, mdst0 = 0, mdst1 = 0;
    bool sender = (warp == 0 && lane < 8 && (uint32_t)lane != rank);
    if (warp == 0 && lane < 8) {
        dst_b0 = mapa_u32(hbase + (uint32_t)(36 * rank) * 4u, (uint32_t)lane);
        dst_b1 = mapa_u32(hbase + (uint32_t)(288 + 36 * rank) * 4u, (uint32_t)lane);
        mdst0 = mapa_u32(mb0, (uint32_t)lane);
        mdst1 = mapa_u32(mb1, (uint32_t)lane);
    }

    __syncthreads();
    asm volatile("barrier.cluster.arrive.aligned;" ::: "memory");
    asm volatile("barrier.cluster.wait.aligned;" ::: "memory");

    float c = 0.f;                 // cell state lives in cb==0 lanes
    uint32_t par0 = 0, par1 = 0;

    for (int s = 0; s < T_LEN; s++) {
        int b = s & 1;
        int si = s & 15;
        int t = dir ? (T_LEN - 1 - s) : s;

        if (si == 0) {
            int c2 = (s >> 4) + 2;
            if (c2 < (T_LEN / 16)) {
                PRE_ISSUE(c2, c2 % 3);
                asm volatile("cp.async.wait_group 2;" ::: "memory");
            } else {
                asm volatile("cp.async.wait_group 0;" ::: "memory");
            }
            __syncthreads();
        }
        int buf = (s >> 4) % 3;

        // pre for gate cb of this unit (only cb<4 lanes need it)
        float p = (cb < 4) ? pre_s[buf][si][cb * 36 + unit] : 0.f;

        // wait until all 7 remote CTAs delivered h for this step
        if (s > 0) {
            if (b) { mbar_wait(mb1, par1); par1 ^= 1; }
            else   { mbar_wait(mb0, par0); par0 ^= 1; }
        }
        if (tid == 0) mbar_expect_tx(b ? mb1 : mb0, 896);

        // matvec: 4 gate rows x 32 cols; h from hsm[b] block cb
        const ulonglong2* h2 = (const ulonglong2*)(&hsm[b][cb * 36]);
        unsigned long long a0 = 0ull, a1 = 0ull, a2 = 0ull, a3 = 0ull;
#pragma unroll
        for (int q = 0; q < 8; q++) {
            ulonglong2 hv = h2[q];
            a0 = ffma2(wr[0][2 * q], hv.x, a0);
            a1 = ffma2(wr[1][2 * q], hv.x, a1);
            a2 = ffma2(wr[2][2 * q], hv.x, a2);
            a3 = ffma2(wr[3][2 * q], hv.x, a3);
            a0 = ffma2(wr[0][2 * q + 1], hv.y, a0);
            a1 = ffma2(wr[1][2 * q + 1], hv.y, a1);
            a2 = ffma2(wr[2][2 * q + 1], hv.y, a2);
            a3 = ffma2(wr[3][2 * q + 1], hv.y, a3);
        }
        float2 f0 = unpackf2(a0), f1 = unpackf2(a1);
        float2 f2 = unpackf2(a2), f3 = unpackf2(a3);
        float s0 = f0.x + f0.y, s1 = f1.x + f1.y;
        float s2 = f2.x + f2.y, s3 = f3.x + f3.y;

        if (cb == 0) s0 += p;
        else if (cb == 1) s1 += p;
        else if (cb == 2) s2 += p;
        else if (cb == 3) s3 += p;

#pragma unroll
        for (int mk = 1; mk < 8; mk <<= 1) {
            s0 += __shfl_xor_sync(0xffffffffu, s0, mk);
            s1 += __shfl_xor_sync(0xffffffffu, s1, mk);
            s2 += __shfl_xor_sync(0xffffffffu, s2, mk);
            s3 += __shfl_xor_sync(0xffffffffu, s3, mk);
        }

        // gates at cb==0 lanes (4 per warp), one unit each
        if (cb == 0) {
            float ii = sigmoidf_(s0);
            float ff = sigmoidf_(s1);
            float oo = sigmoidf_(s3);
            c = ff * c + ii * tanh_fast(s2);
            float h = oo * tanh_fast(c);
            hstage[b ^ 1][unit] = h;
            hsm[b ^ 1][36 * (int)rank + unit] = h;   // self-delivery (local)
            hout[(size_t)t * H_DIM + k_unit] = h;    // off critical path
        }
        __syncthreads();   // hstage + local hsm staged; hsm[b] reads retired

        // warp 0 lanes 0-7 (minus self): ship 128B block to CTA 'lane'
        if (sender) {
            asm volatile("fence.proxy.async.shared::cta;" ::: "memory");
            uint32_t d = b ? dst_b0 : dst_b1;   // step-s output -> buffer b^1
            uint32_t m = b ? mdst0 : mdst1;
            bulk_s2cluster(d, sbase + (uint32_t)((b ^ 1) * 32) * 4u, 128u, m);
        }
    }

    // drain: final sends (step T-1, odd) targeted mb0; complete that phase
    mbar_wait(mb0, par0);
    asm volatile("barrier.cluster.arrive.aligned;" ::: "memory");
    asm volatile("barrier.cluster.wait.aligned;" ::: "memory");
#undef PRE_ISSUE
}

// ---------------- 3) emit: 16 timesteps per block, W_out SMEM-cached -------
__global__ __launch_bounds__(128) void emit_kernel(
    const float* __restrict__ Wout, const float* __restrict__ bout) {
    int t0 = blockIdx.x * 16;
    __shared__ float Wsm[L_TAGS * 512];     // 36 KB
    __shared__ float h[512];
    __shared__ float part[4][18];
    int tid = threadIdx.x;

    for (int i = tid; i < L_TAGS * 512; i += 128) Wsm[i] = Wout[i];

    for (int tl = 0; tl < 16; tl++) {
        int t = t0 + tl;
        __syncthreads();            // also covers Wsm on first iteration
        h[tid]       = g_h[0][(size_t)t * 256 + tid];
        h[tid + 128] = g_h[0][(size_t)t * 256 + 128 + tid];
        h[tid + 256] = g_h[1][(size_t)t * 256 + tid];
        h[tid + 384] = g_h[1][(size_t)t * 256 + 128 + tid];
        __syncthreads();

        if (tid < 72) {
            int jj = tid >> 2, q = tid & 3;
            const float* w = Wsm + jj * 512 + q * 128;
            const float* hh = h + q * 128;
            float a0 = 0.f, a1 = 0.f, a2 = 0.f, a3 = 0.f;
#pragma unroll
            for (int k = 0; k < 128; k += 4) {
                a0 += hh[k] * w[k];
                a1 += hh[k + 1] * w[k + 1];
                a2 += hh[k + 2] * w[k + 2];
                a3 += hh[k + 3] * w[k + 3];
            }
            part[q][jj] = (a0 + a1) + (a2 + a3);
        }
        __syncthreads();
        if (tid < 18)
            g_emit[(size_t)t * L_TAGS + tid] =
                part[0][tid] + part[1][tid] + part[2][tid] + part[3][tid] +
                bout[tid];
    }
}

// ---------------- 4) Viterbi + backtrack (one warp) -------------------------
__global__ void viterbi_kernel(const float* __restrict__ trans,
                               float* __restrict__ out, int write_score) {
    extern __shared__ unsigned char bp[];
    int j = threadIdx.x;
    bool act = (j < L_TAGS);

    float tcol[L_TAGS];
#pragma unroll
    for (int i = 0; i < L_TAGS; i++)
        tcol[i] = act ? trans[i * L_TAGS + j] : 0.f;

    float fv = act ? ((j == START_TAG) ? 0.f : NEGV) : -3.0e38f;
    float e = act ? g_emit[j] : 0.f;

    for (int t = 0; t < T_LEN; t++) {
        float e_next = (act && t + 1 < T_LEN)
                           ? g_emit[(size_t)(t + 1) * L_TAGS + j] : 0.f;
        // 6 independent chains of 3, merged in ascending order with strict >
        // (keeps first-maximum semantics, matching jnp.argmax)
        float bb[6];
        int aa[6];
#pragma unroll
        for (int ch = 0; ch < 6; ch++) { bb[ch] = -3.4e38f; aa[ch] = ch * 3; }
#pragma unroll
        for (int k = 0; k < 3; k++) {
#pragma unroll
            for (int ch = 0; ch < 6; ch++) {
                int i = ch * 3 + k;
                float sv = __shfl_sync(0xffffffffu, fv, i) + tcol[i];
                if (sv > bb[ch]) { bb[ch] = sv; aa[ch] = i; }
            }
        }
        float best = bb[0]; int arg = aa[0];
#pragma unroll
        for (int ch = 1; ch < 6; ch++)
            if (bb[ch] > best) { best = bb[ch]; arg = aa[ch]; }

        if (act) {
            bp[t * L_TAGS + j] = (unsigned char)arg;
            fv = best + e;
        }
        e = e_next;
    }

    float term = act ? (fv + trans[j * L_TAGS + STOP_TAG]) : -3.4e38f;
    int ai = j;
#pragma unroll
    for (int off = 16; off > 0; off >>= 1) {
        float ov = __shfl_xor_sync(0xffffffffu, term, off);
        int oi = __shfl_xor_sync(0xffffffffu, ai, off);
        if (ov > term || (ov == term && oi < ai)) { term = ov; ai = oi; }
    }

    if (j == 0) {
        if (write_score) out[0] = term;
        float* path = out + write_score;
        int tag = ai;
        for (int t = T_LEN - 1; t >= 0; t--) {
            path[t] = (float)tag;
            tag = bp[t * L_TAGS + tag];
        }
    }
}

// ---------------- launch ----------------------------------------------------
extern "C" void kernel_launch(void* const* d_in, const int* in_sizes, int n_in,
                              void* d_out, int out_size) {
    const int*   feats  = (const int*)d_in[0];
    const float* emb    = (const float*)d_in[1];
    const float* w_ih_f = (const float*)d_in[2];
    const float* w_hh_f = (const float*)d_in[3];
    const float* b_f    = (const float*)d_in[4];
    const float* w_ih_b = (const float*)d_in[5];
    const float* w_hh_b = (const float*)d_in[6];
    const float* b_b    = (const float*)d_in[7];
    const float* W_out  = (const float*)d_in[8];
    const float* b_out  = (const float*)d_in[9];
    const float* trans  = (const float*)d_in[10];

    dim3 gg(G_DIM / 64, T_LEN / 64, 2);
    gemm_pre_kernel<<<gg, 256>>>(feats, emb, w_ih_f, w_ih_b, b_f, b_b);

    lstm_cluster_kernel<<<16, 256>>>(w_hh_f, w_hh_b);

    emit_kernel<<<T_LEN / 16, 128>>>(W_out, b_out);

    int ws = (out_size > T_LEN) ? 1 : 0;   // layout: [path_score, path...]
    static int smem_set = 0;
    if (!smem_set) {
        cudaFuncSetAttribute(viterbi_kernel,
                             cudaFuncAttributeMaxDynamicSharedMemorySize,
                             T_LEN * L_TAGS + 1024);
        smem_set = 1;
    }
    viterbi_kernel<<<1, 32, T_LEN * L_TAGS>>>(trans, (float*)d_out, ws);
}